// round 2
// baseline (speedup 1.0000x reference)
#include <cuda_runtime.h>
#include <cuda_bf16.h>
#include <math.h>

// Problem constants
#define BATCH 8
#define SEQ   2048
#define DIM   768
#define MTOT  (BATCH * SEQ)   // 16384

// GEMM tile config
#define BM 128
#define BN 128
#define BK 16

// Scratch (device globals: allocation-free rule)
__device__ float g_q[BATCH * SEQ * DIM];
__device__ float g_k[BATCH * SEQ * DIM];
__device__ float g_v[BATCH * SEQ * DIM];
__device__ float g_s[(size_t)BATCH * SEQ * SEQ];   // scores / probs (134 MB)
__device__ float g_m[BATCH * SEQ * DIM];           // merged

// ---------------------------------------------------------------------------
// Tiled SGEMM: C = A * op(B) + bias
//   A:  [M, K] row-major (K contiguous)
//   B_KMAJOR=true : B is [Nc, K] row-major  -> C = A @ B^T   (torch Linear)
//   B_KMAJOR=false: B is [K, Nc] row-major  -> C = A @ B
//   blockIdx.z batches with strides sA/sB/sC (elements).
// ---------------------------------------------------------------------------
template <bool B_KMAJOR>
__global__ __launch_bounds__(256) void sgemm_kernel(
    const float* __restrict__ A, const float* __restrict__ B,
    const float* __restrict__ bias, float* __restrict__ C,
    int M, int Nc, int K,
    long long sA, long long sB, long long sC)
{
    __shared__ float As[BK][BM];
    __shared__ float Bs[BK][BN];

    const int bz = blockIdx.z;
    A += bz * sA; B += bz * sB; C += bz * sC;

    const int row0 = blockIdx.y * BM;
    const int col0 = blockIdx.x * BN;
    const int tid  = threadIdx.x;
    const int tm   = tid >> 4;          // 0..15
    const int tn   = tid & 15;          // 0..15

    float acc[8][8];
#pragma unroll
    for (int i = 0; i < 8; i++)
#pragma unroll
        for (int j = 0; j < 8; j++) acc[i][j] = 0.f;

    for (int k0 = 0; k0 < K; k0 += BK) {
        // --- load A tile (128 x 16), store transposed As[k][m] ---
#pragma unroll
        for (int it = 0; it < 2; it++) {
            int f  = tid + it * 256;        // 0..511 float4 slots
            int r  = f >> 2;                // 0..127
            int c4 = (f & 3) * 4;           // 0,4,8,12
            float4 v = *(const float4*)&A[(long long)(row0 + r) * K + k0 + c4];
            As[c4 + 0][r] = v.x; As[c4 + 1][r] = v.y;
            As[c4 + 2][r] = v.z; As[c4 + 3][r] = v.w;
        }
        // --- load B tile ---
        if (B_KMAJOR) {
#pragma unroll
            for (int it = 0; it < 2; it++) {
                int f  = tid + it * 256;
                int r  = f >> 2;            // B row = output col
                int c4 = (f & 3) * 4;
                float4 v = *(const float4*)&B[(long long)(col0 + r) * K + k0 + c4];
                Bs[c4 + 0][r] = v.x; Bs[c4 + 1][r] = v.y;
                Bs[c4 + 2][r] = v.z; Bs[c4 + 3][r] = v.w;
            }
        } else {
#pragma unroll
            for (int it = 0; it < 2; it++) {
                int f  = tid + it * 256;
                int r  = f >> 5;            // 0..15 (k within tile)
                int c4 = (f & 31) * 4;      // 0..124
                float4 v = *(const float4*)&B[(long long)(k0 + r) * Nc + col0 + c4];
                *(float4*)&Bs[r][c4] = v;
            }
        }
        __syncthreads();

#pragma unroll
        for (int kk = 0; kk < BK; kk++) {
            float a[8], b[8];
            *(float4*)&a[0] = *(const float4*)&As[kk][tm * 4];
            *(float4*)&a[4] = *(const float4*)&As[kk][tm * 4 + 64];
            *(float4*)&b[0] = *(const float4*)&Bs[kk][tn * 4];
            *(float4*)&b[4] = *(const float4*)&Bs[kk][tn * 4 + 64];
#pragma unroll
            for (int i = 0; i < 8; i++)
#pragma unroll
                for (int j = 0; j < 8; j++)
                    acc[i][j] += a[i] * b[j];
        }
        __syncthreads();
    }

    // --- epilogue ---
#pragma unroll
    for (int i = 0; i < 8; i++) {
        int r = row0 + ((i < 4) ? (tm * 4 + i) : (64 + tm * 4 + i - 4));
#pragma unroll
        for (int jj = 0; jj < 2; jj++) {
            int c = col0 + jj * 64 + tn * 4;
            float4 v;
            v.x = acc[i][jj * 4 + 0];
            v.y = acc[i][jj * 4 + 1];
            v.z = acc[i][jj * 4 + 2];
            v.w = acc[i][jj * 4 + 3];
            if (bias) {
                v.x += bias[c + 0]; v.y += bias[c + 1];
                v.z += bias[c + 2]; v.w += bias[c + 3];
            }
            *(float4*)&C[(long long)r * Nc + c] = v;
        }
    }
}

// ---------------------------------------------------------------------------
// Row softmax over keys with key mask (-inf) and query-mask scaling.
// One block (256 threads) per row of S [B*SEQ rows, SEQ cols].
// ---------------------------------------------------------------------------
__device__ __forceinline__ float warp_max(float v) {
#pragma unroll
    for (int o = 16; o > 0; o >>= 1) v = fmaxf(v, __shfl_xor_sync(0xffffffffu, v, o));
    return v;
}
__device__ __forceinline__ float warp_sum(float v) {
#pragma unroll
    for (int o = 16; o > 0; o >>= 1) v += __shfl_xor_sync(0xffffffffu, v, o);
    return v;
}

__global__ __launch_bounds__(256) void softmax_kernel(
    float* __restrict__ S, const int* __restrict__ mask)
{
    const long long row = blockIdx.x;          // b*SEQ + q
    const int b = (int)(row / SEQ);
    const int q = (int)(row % SEQ);
    float* __restrict__ Srow = S + row * (long long)SEQ;
    const int* __restrict__ mrow = mask + (long long)b * SEQ;
    const int qm = mrow[q];

    __shared__ float red_max[8];
    __shared__ float red_sum[8];
    const int tid = threadIdx.x;
    const int wid = tid >> 5, lid = tid & 31;

    float vals[8];
    float m = -INFINITY;
#pragma unroll
    for (int i = 0; i < 8; i++) {
        int j = tid + i * 256;
        float s = mrow[j] ? Srow[j] : -INFINITY;
        vals[i] = s;
        m = fmaxf(m, s);
    }
    m = warp_max(m);
    if (lid == 0) red_max[wid] = m;
    __syncthreads();
    {
        float t = (lid < 8) ? red_max[lid] : -INFINITY;
        m = warp_max(t);   // all lanes hold block max
    }

    float sum = 0.f;
#pragma unroll
    for (int i = 0; i < 8; i++) {
        float e = __expf(vals[i] - m);
        vals[i] = e;
        sum += e;
    }
    sum = warp_sum(sum);
    if (lid == 0) red_sum[wid] = sum;
    __syncthreads();
    {
        float t = (lid < 8) ? red_sum[lid] : 0.f;
        sum = warp_sum(t); // all lanes hold block sum
    }

    const float scale = qm ? (1.f / sum) : 0.f;  // fold query mask into P
#pragma unroll
    for (int i = 0; i < 8; i++) {
        int j = tid + i * 256;
        Srow[j] = vals[i] * scale;
    }
}

// ---------------------------------------------------------------------------
extern "C" void kernel_launch(void* const* d_in, const int* in_sizes, int n_in,
                              void* d_out, int out_size)
{
    const float* query = (const float*)d_in[0];
    const float* value = (const float*)d_in[1];
    const int*   mask  = (const int*)  d_in[2];
    const float* q_w   = (const float*)d_in[3];
    const float* q_b   = (const float*)d_in[4];
    const float* k_w   = (const float*)d_in[5];
    const float* k_b   = (const float*)d_in[6];
    const float* v_w   = (const float*)d_in[7];
    const float* v_b   = (const float*)d_in[8];
    const float* fc_w  = (const float*)d_in[9];
    const float* fc_b  = (const float*)d_in[10];
    float* out = (float*)d_out;

    float *q_ptr, *k_ptr, *v_ptr, *s_ptr, *m_ptr;
    cudaGetSymbolAddress((void**)&q_ptr, g_q);
    cudaGetSymbolAddress((void**)&k_ptr, g_k);
    cudaGetSymbolAddress((void**)&v_ptr, g_v);
    cudaGetSymbolAddress((void**)&s_ptr, g_s);
    cudaGetSymbolAddress((void**)&m_ptr, g_m);

    dim3 blk(256);

    // 1) Projections: [16384,768] = X @ W^T + b
    {
        dim3 grid(DIM / BN, MTOT / BM, 1);
        sgemm_kernel<true><<<grid, blk>>>(query, q_w, q_b, q_ptr, MTOT, DIM, DIM, 0, 0, 0);
        sgemm_kernel<true><<<grid, blk>>>(value, k_w, k_b, k_ptr, MTOT, DIM, DIM, 0, 0, 0);
        sgemm_kernel<true><<<grid, blk>>>(value, v_w, v_b, v_ptr, MTOT, DIM, DIM, 0, 0, 0);
    }

    // 2) Scores: S[b] = Q[b] @ K[b]^T   (batched, 2048x2048x768)
    {
        dim3 grid(SEQ / BN, SEQ / BM, BATCH);
        sgemm_kernel<true><<<grid, blk>>>(q_ptr, k_ptr, nullptr, s_ptr,
                                          SEQ, SEQ, DIM,
                                          (long long)SEQ * DIM, (long long)SEQ * DIM,
                                          (long long)SEQ * SEQ);
    }

    // 3) Masked softmax over keys (+ query-mask scaling), in place
    softmax_kernel<<<BATCH * SEQ, blk>>>(s_ptr, mask);

    // 4) Merged: M[b] = P[b] @ V[b]   (batched, 2048x768x2048, B not transposed)
    {
        dim3 grid(DIM / BN, SEQ / BM, BATCH);
        sgemm_kernel<false><<<grid, blk>>>(s_ptr, v_ptr, nullptr, m_ptr,
                                           SEQ, DIM, SEQ,
                                           (long long)SEQ * SEQ, (long long)SEQ * DIM,
                                           (long long)SEQ * DIM);
    }

    // 5) Output projection: out = M @ fc_w^T + fc_b
    {
        dim3 grid(DIM / BN, MTOT / BM, 1);
        sgemm_kernel<true><<<grid, blk>>>(m_ptr, fc_w, fc_b, out, MTOT, DIM, DIM, 0, 0, 0);
    }
}

// round 4
// speedup vs baseline: 2.0556x; 2.0556x over previous
#include <cuda_runtime.h>
#include <cuda_bf16.h>
#include <math.h>
#include <stdint.h>

typedef __nv_bfloat16 bf16;

#define BATCH 8
#define SEQ   2048
#define DIM   768
#define MTOT  (BATCH * SEQ)     // 16384

// ---- GEMM tile config (mma.sync path, sm_103-safe) ----
#define BM 128
#define BN 128
#define BK 32
#define ROWB 80                      // padded row bytes (32 bf16 = 64B data + 16B pad)
#define MAT_BYTES (128 * ROWB)       // 10240 per matrix-half
#define STAGE_BYTES (4 * MAT_BYTES)  // Ah, Al, Bh, Bl = 40960
#define NSTAGES 3
#define GEMM_SMEM (NSTAGES * STAGE_BYTES)   // 122880

// ---------------- device scratch (allocation-free rule) ----------------
__device__ bf16 g_xh[MTOT * DIM], g_xl[MTOT * DIM];     // query split
__device__ bf16 g_yh[MTOT * DIM], g_yl[MTOT * DIM];     // value split
__device__ bf16 g_wqh[DIM * DIM], g_wql[DIM * DIM];
__device__ bf16 g_wkh[DIM * DIM], g_wkl[DIM * DIM];
__device__ bf16 g_wvh[DIM * DIM], g_wvl[DIM * DIM];
__device__ bf16 g_wfh[DIM * DIM], g_wfl[DIM * DIM];
__device__ bf16 g_qh[MTOT * DIM], g_ql[MTOT * DIM];     // Q proj split
__device__ bf16 g_kh[MTOT * DIM], g_kl[MTOT * DIM];     // K proj split
__device__ float g_v[MTOT * DIM];                        // V proj fp32
__device__ bf16 g_vth[MTOT * DIM], g_vtl[MTOT * DIM];   // V^T split [B][DIM][SEQ]
__device__ float g_s[(size_t)BATCH * SEQ * SEQ];         // scores fp32 (134MB)
__device__ bf16 g_ph[(size_t)BATCH * SEQ * SEQ];         // probs split
__device__ bf16 g_pl[(size_t)BATCH * SEQ * SEQ];
__device__ bf16 g_mh[MTOT * DIM], g_ml[MTOT * DIM];     // merged split

// ---------------- PTX helpers (all plain-sm_103 legal) ----------------
__device__ __forceinline__ uint32_t smem_u32(const void* p) {
    uint32_t a;
    asm("{ .reg .u64 t; cvta.to.shared.u64 t, %1; cvt.u32.u64 %0, t; }" : "=r"(a) : "l"(p));
    return a;
}
__device__ __forceinline__ void cp16(uint32_t s, const void* g) {
    asm volatile("cp.async.cg.shared.global [%0], [%1], 16;" :: "r"(s), "l"(g));
}
__device__ __forceinline__ void cp_commit() { asm volatile("cp.async.commit_group;" ::: "memory"); }
template <int N> __device__ __forceinline__ void cp_wait() {
    asm volatile("cp.async.wait_group %0;" :: "n"(N) : "memory");
}
__device__ __forceinline__ void ldmat_x4(uint32_t* r, uint32_t addr) {
    asm volatile("ldmatrix.sync.aligned.m8n8.x4.shared.b16 {%0,%1,%2,%3}, [%4];"
                 : "=r"(r[0]), "=r"(r[1]), "=r"(r[2]), "=r"(r[3]) : "r"(addr));
}
__device__ __forceinline__ void mma_bf16(float* c, const uint32_t* a, uint32_t b0, uint32_t b1) {
    asm volatile(
        "mma.sync.aligned.m16n8k16.row.col.f32.bf16.bf16.f32 "
        "{%0,%1,%2,%3}, {%4,%5,%6,%7}, {%8,%9}, {%0,%1,%2,%3};"
        : "+f"(c[0]), "+f"(c[1]), "+f"(c[2]), "+f"(c[3])
        : "r"(a[0]), "r"(a[1]), "r"(a[2]), "r"(a[3]), "r"(b0), "r"(b1));
}

// ---------------------------------------------------------------------------
// mma.sync GEMM: C[M,N] = A[M,K] * B[N,K]^T (+bias), 3-term bf16 split.
// A,B row-major with K contiguous. EPI=0: fp32 C. EPI=1: bf16 hi/lo split C.
// grid: (N/BN, M/BM, batch); block: 256 threads (8 warps of 64x32).
// ---------------------------------------------------------------------------
template <int EPI>
__global__ __launch_bounds__(256, 1) void gemm_mma(
    const bf16* __restrict__ Agh, const bf16* __restrict__ Agl,
    const bf16* __restrict__ Bgh, const bf16* __restrict__ Bgl,
    const float* __restrict__ bias,
    float* __restrict__ C, bf16* __restrict__ Ch, bf16* __restrict__ Cl,
    int M, int N, int K,
    long long sA, long long sB, long long sC)
{
    extern __shared__ char smem[];
    const int tid = threadIdx.x;
    const int wid = tid >> 5;
    const int lane = tid & 31;
    const int bz = blockIdx.z;
    Agh += bz * sA; Agl += bz * sA;
    Bgh += bz * sB; Bgl += bz * sB;
    const long long coff = bz * sC;

    const int row0 = blockIdx.y * BM;
    const int col0 = blockIdx.x * BN;
    const uint32_t smem_base = smem_u32(smem);

    const int wm = (wid >> 2) * 64;   // warp m offset in tile
    const int wn = (wid & 3) * 32;    // warp n offset in tile

    float acc[4][4][4];
#pragma unroll
    for (int i = 0; i < 4; i++)
#pragma unroll
        for (int j = 0; j < 4; j++)
#pragma unroll
            for (int t = 0; t < 4; t++) acc[i][j][t] = 0.f;

    const int NS = K / BK;

    auto load_stage = [&](int st, int k0) {
        const uint32_t base = smem_base + (uint32_t)(st * STAGE_BYTES);
#pragma unroll
        for (int i = 0; i < 2; i++) {              // A: 128 rows x 4 chunks
            int idx = tid + i * 256;
            int r = idx >> 2, c = idx & 3;
            uint32_t s = base + r * ROWB + c * 16;
            size_t g = (size_t)(row0 + r) * K + k0 + c * 8;
            cp16(s, Agh + g);
            cp16(s + MAT_BYTES, Agl + g);
        }
#pragma unroll
        for (int i = 0; i < 2; i++) {              // B: 128 rows x 4 chunks
            int idx = tid + i * 256;
            int r = idx >> 2, c = idx & 3;
            uint32_t s = base + 2 * MAT_BYTES + r * ROWB + c * 16;
            size_t g = (size_t)(col0 + r) * K + k0 + c * 8;
            cp16(s, Bgh + g);
            cp16(s + MAT_BYTES, Bgl + g);
        }
        cp_commit();
    };

    // ldmatrix lane address components
    const int lrow = lane & 15;            // A: row within m16
    const int lkh  = lane >> 4;            // A: k half (0/1)
    const int brow = (lane & 7) + ((lane >> 4) << 3);   // B: n row within n16
    const int bkh  = (lane >> 3) & 1;                   // B: k half

    load_stage(0, 0);
    load_stage(1, BK);

    for (int s = 0; s < NS; s++) {
        cp_wait<1>();            // stage s complete (only s+1 may be pending)
        __syncthreads();
        if (s + 2 < NS) load_stage((s + 2) % NSTAGES, (s + 2) * BK);

        const uint32_t base = smem_base + (uint32_t)((s % NSTAGES) * STAGE_BYTES);
        const uint32_t aB = base;
        const uint32_t bB = base + 2 * MAT_BYTES;

#pragma unroll
        for (int ks = 0; ks < 2; ks++) {
            uint32_t afh[4][4], afl[4][4];
#pragma unroll
            for (int im = 0; im < 4; im++) {
                uint32_t ad = aB + (uint32_t)((wm + im * 16 + lrow) * ROWB + ks * 32 + lkh * 16);
                ldmat_x4(afh[im], ad);
                ldmat_x4(afl[im], ad + MAT_BYTES);
            }
            uint32_t bfh[2][4], bfl[2][4];
#pragma unroll
            for (int ib = 0; ib < 2; ib++) {
                uint32_t bd = bB + (uint32_t)((wn + ib * 16 + brow) * ROWB + ks * 32 + bkh * 16);
                ldmat_x4(bfh[ib], bd);
                ldmat_x4(bfl[ib], bd + MAT_BYTES);
            }
#pragma unroll
            for (int im = 0; im < 4; im++) {
#pragma unroll
                for (int in4 = 0; in4 < 4; in4++) {
                    const int ib = in4 >> 1, hf = (in4 & 1) * 2;
                    mma_bf16(acc[im][in4], afh[im], bfh[ib][hf], bfh[ib][hf + 1]);
                    mma_bf16(acc[im][in4], afh[im], bfl[ib][hf], bfl[ib][hf + 1]);
                    mma_bf16(acc[im][in4], afl[im], bfh[ib][hf], bfh[ib][hf + 1]);
                }
            }
        }
        __syncthreads();
    }

    // ---- epilogue ----
    const int lane4 = lane >> 2;
    const int lanec = (lane & 3) * 2;
#pragma unroll
    for (int im = 0; im < 4; im++) {
#pragma unroll
        for (int in4 = 0; in4 < 4; in4++) {
            const int m0 = row0 + wm + im * 16 + lane4;
            const int nc = col0 + wn + in4 * 8 + lanec;
            float b0 = bias ? bias[nc] : 0.f;
            float b1 = bias ? bias[nc + 1] : 0.f;
            float v00 = acc[im][in4][0] + b0, v01 = acc[im][in4][1] + b1;
            float v10 = acc[im][in4][2] + b0, v11 = acc[im][in4][3] + b1;
            if (EPI == 0) {
                *(float2*)&C[coff + (long long)m0 * N + nc]       = make_float2(v00, v01);
                *(float2*)&C[coff + (long long)(m0 + 8) * N + nc] = make_float2(v10, v11);
            } else {
                bf16 h[2], l[2];
                h[0] = __float2bfloat16_rn(v00); l[0] = __float2bfloat16_rn(v00 - __bfloat162float(h[0]));
                h[1] = __float2bfloat16_rn(v01); l[1] = __float2bfloat16_rn(v01 - __bfloat162float(h[1]));
                *(uint32_t*)&Ch[coff + (long long)m0 * N + nc] = *(uint32_t*)h;
                *(uint32_t*)&Cl[coff + (long long)m0 * N + nc] = *(uint32_t*)l;
                h[0] = __float2bfloat16_rn(v10); l[0] = __float2bfloat16_rn(v10 - __bfloat162float(h[0]));
                h[1] = __float2bfloat16_rn(v11); l[1] = __float2bfloat16_rn(v11 - __bfloat162float(h[1]));
                *(uint32_t*)&Ch[coff + (long long)(m0 + 8) * N + nc] = *(uint32_t*)h;
                *(uint32_t*)&Cl[coff + (long long)(m0 + 8) * N + nc] = *(uint32_t*)l;
            }
        }
    }
}

// ---------------------------------------------------------------------------
// fp32 -> bf16 hi/lo split (elementwise, float4 vectorized)
// ---------------------------------------------------------------------------
__global__ __launch_bounds__(256) void split_kernel(
    const float* __restrict__ x, bf16* __restrict__ h, bf16* __restrict__ l, int n4)
{
    int i = blockIdx.x * 256 + threadIdx.x;
    if (i >= n4) return;
    float4 v = *(const float4*)&x[i * 4];
    bf16 hb[4], lb[4];
    float f[4] = {v.x, v.y, v.z, v.w};
#pragma unroll
    for (int j = 0; j < 4; j++) {
        hb[j] = __float2bfloat16_rn(f[j]);
        lb[j] = __float2bfloat16_rn(f[j] - __bfloat162float(hb[j]));
    }
    *(uint2*)&h[i * 4] = *(uint2*)hb;
    *(uint2*)&l[i * 4] = *(uint2*)lb;
}

// ---------------------------------------------------------------------------
// V [B,SEQ,DIM] fp32 -> V^T [B,DIM,SEQ] bf16 hi/lo
// ---------------------------------------------------------------------------
__global__ __launch_bounds__(256) void transpose_split_kernel(
    const float* __restrict__ V, bf16* __restrict__ Th, bf16* __restrict__ Tl)
{
    __shared__ float tile[32][33];
    const int b = blockIdx.z;
    const float* Vb = V + (size_t)b * SEQ * DIM;
    bf16* Thb = Th + (size_t)b * DIM * SEQ;
    bf16* Tlb = Tl + (size_t)b * DIM * SEQ;
    const int d0 = blockIdx.x * 32;
    const int n0 = blockIdx.y * 32;
    const int tx = threadIdx.x, ty = threadIdx.y;
#pragma unroll
    for (int i = 0; i < 4; i++) {
        int n = n0 + ty + i * 8;
        tile[ty + i * 8][tx] = Vb[(size_t)n * DIM + d0 + tx];
    }
    __syncthreads();
#pragma unroll
    for (int i = 0; i < 4; i++) {
        int d = d0 + ty + i * 8;
        int n = n0 + tx;
        float v = tile[tx][ty + i * 8];
        bf16 h = __float2bfloat16_rn(v);
        bf16 l = __float2bfloat16_rn(v - __bfloat162float(h));
        Thb[(size_t)d * SEQ + n] = h;
        Tlb[(size_t)d * SEQ + n] = l;
    }
}

// ---------------------------------------------------------------------------
// Masked softmax: reads fp32 S, writes bf16 hi/lo P (query mask folded in)
// ---------------------------------------------------------------------------
__device__ __forceinline__ float warp_max(float v) {
#pragma unroll
    for (int o = 16; o > 0; o >>= 1) v = fmaxf(v, __shfl_xor_sync(0xffffffffu, v, o));
    return v;
}
__device__ __forceinline__ float warp_sum(float v) {
#pragma unroll
    for (int o = 16; o > 0; o >>= 1) v += __shfl_xor_sync(0xffffffffu, v, o);
    return v;
}

__global__ __launch_bounds__(256) void softmax_kernel(
    const float* __restrict__ S, const int* __restrict__ mask,
    bf16* __restrict__ Ph, bf16* __restrict__ Pl)
{
    const long long row = blockIdx.x;          // b*SEQ + q
    const int b = (int)(row / SEQ);
    const int q = (int)(row % SEQ);
    const float* __restrict__ Srow = S + row * (long long)SEQ;
    const int* __restrict__ mrow = mask + (long long)b * SEQ;
    const int qm = mrow[q];

    __shared__ float red_max[8];
    __shared__ float red_sum[8];
    const int tid = threadIdx.x;
    const int wid = tid >> 5, lid = tid & 31;

    float vals[8];
    float m = -INFINITY;
#pragma unroll
    for (int i = 0; i < 8; i++) {
        int j = tid + i * 256;
        float s = mrow[j] ? Srow[j] : -INFINITY;
        vals[i] = s;
        m = fmaxf(m, s);
    }
    m = warp_max(m);
    if (lid == 0) red_max[wid] = m;
    __syncthreads();
    { float t = (lid < 8) ? red_max[lid] : -INFINITY; m = warp_max(t); }

    float sum = 0.f;
#pragma unroll
    for (int i = 0; i < 8; i++) {
        float e = __expf(vals[i] - m);
        vals[i] = e;
        sum += e;
    }
    sum = warp_sum(sum);
    if (lid == 0) red_sum[wid] = sum;
    __syncthreads();
    { float t = (lid < 8) ? red_sum[lid] : 0.f; sum = warp_sum(t); }

    const float scale = qm ? (1.f / sum) : 0.f;
#pragma unroll
    for (int i = 0; i < 8; i++) {
        int j = tid + i * 256;
        float p = vals[i] * scale;
        bf16 h = __float2bfloat16_rn(p);
        bf16 l = __float2bfloat16_rn(p - __bfloat162float(h));
        Ph[row * (long long)SEQ + j] = h;
        Pl[row * (long long)SEQ + j] = l;
    }
}

// ---------------------------------------------------------------------------
extern "C" void kernel_launch(void* const* d_in, const int* in_sizes, int n_in,
                              void* d_out, int out_size)
{
    const float* query = (const float*)d_in[0];
    const float* value = (const float*)d_in[1];
    const int*   mask  = (const int*)  d_in[2];
    const float* q_w   = (const float*)d_in[3];
    const float* q_b   = (const float*)d_in[4];
    const float* k_w   = (const float*)d_in[5];
    const float* k_b   = (const float*)d_in[6];
    const float* v_w   = (const float*)d_in[7];
    const float* v_b   = (const float*)d_in[8];
    const float* fc_w  = (const float*)d_in[9];
    const float* fc_b  = (const float*)d_in[10];
    float* out = (float*)d_out;

    cudaFuncSetAttribute(gemm_mma<0>, cudaFuncAttributeMaxDynamicSharedMemorySize, GEMM_SMEM);
    cudaFuncSetAttribute(gemm_mma<1>, cudaFuncAttributeMaxDynamicSharedMemorySize, GEMM_SMEM);

    bf16 *xh, *xl, *yh, *yl, *wqh, *wql, *wkh, *wkl, *wvh, *wvl, *wfh, *wfl;
    bf16 *qh, *ql, *kh, *kl, *vth, *vtl, *ph, *pl, *mh, *ml;
    float *v_ptr, *s_ptr;
    cudaGetSymbolAddress((void**)&xh, g_xh);   cudaGetSymbolAddress((void**)&xl, g_xl);
    cudaGetSymbolAddress((void**)&yh, g_yh);   cudaGetSymbolAddress((void**)&yl, g_yl);
    cudaGetSymbolAddress((void**)&wqh, g_wqh); cudaGetSymbolAddress((void**)&wql, g_wql);
    cudaGetSymbolAddress((void**)&wkh, g_wkh); cudaGetSymbolAddress((void**)&wkl, g_wkl);
    cudaGetSymbolAddress((void**)&wvh, g_wvh); cudaGetSymbolAddress((void**)&wvl, g_wvl);
    cudaGetSymbolAddress((void**)&wfh, g_wfh); cudaGetSymbolAddress((void**)&wfl, g_wfl);
    cudaGetSymbolAddress((void**)&qh, g_qh);   cudaGetSymbolAddress((void**)&ql, g_ql);
    cudaGetSymbolAddress((void**)&kh, g_kh);   cudaGetSymbolAddress((void**)&kl, g_kl);
    cudaGetSymbolAddress((void**)&v_ptr, g_v);
    cudaGetSymbolAddress((void**)&vth, g_vth); cudaGetSymbolAddress((void**)&vtl, g_vtl);
    cudaGetSymbolAddress((void**)&s_ptr, g_s);
    cudaGetSymbolAddress((void**)&ph, g_ph);   cudaGetSymbolAddress((void**)&pl, g_pl);
    cudaGetSymbolAddress((void**)&mh, g_mh);   cudaGetSymbolAddress((void**)&ml, g_ml);

    // 1) split inputs + weights to bf16 hi/lo
    {
        int n4 = MTOT * DIM / 4;
        split_kernel<<<(n4 + 255) / 256, 256>>>(query, xh, xl, n4);
        split_kernel<<<(n4 + 255) / 256, 256>>>(value, yh, yl, n4);
        int w4 = DIM * DIM / 4;
        split_kernel<<<(w4 + 255) / 256, 256>>>(q_w,  wqh, wql, w4);
        split_kernel<<<(w4 + 255) / 256, 256>>>(k_w,  wkh, wkl, w4);
        split_kernel<<<(w4 + 255) / 256, 256>>>(v_w,  wvh, wvl, w4);
        split_kernel<<<(w4 + 255) / 256, 256>>>(fc_w, wfh, wfl, w4);
    }

    // 2) projections (M=16384, N=768, K=768)
    {
        dim3 grid(DIM / BN, MTOT / BM, 1);
        gemm_mma<1><<<grid, 256, GEMM_SMEM>>>(xh, xl, wqh, wql, q_b, nullptr, qh, ql,
                                              MTOT, DIM, DIM, 0, 0, 0);
        gemm_mma<1><<<grid, 256, GEMM_SMEM>>>(yh, yl, wkh, wkl, k_b, nullptr, kh, kl,
                                              MTOT, DIM, DIM, 0, 0, 0);
        gemm_mma<0><<<grid, 256, GEMM_SMEM>>>(yh, yl, wvh, wvl, v_b, v_ptr, nullptr, nullptr,
                                              MTOT, DIM, DIM, 0, 0, 0);
    }

    // 3) transpose+split V
    {
        dim3 grid(DIM / 32, SEQ / 32, BATCH);
        transpose_split_kernel<<<grid, dim3(32, 8)>>>(v_ptr, vth, vtl);
    }

    // 4) scores S[b] = Q[b] @ K[b]^T  (M=N=2048, K=768, batched)
    {
        dim3 grid(SEQ / BN, SEQ / BM, BATCH);
        gemm_mma<0><<<grid, 256, GEMM_SMEM>>>(qh, ql, kh, kl, nullptr, s_ptr, nullptr, nullptr,
                                              SEQ, SEQ, DIM,
                                              (long long)SEQ * DIM, (long long)SEQ * DIM,
                                              (long long)SEQ * SEQ);
    }

    // 5) masked softmax -> P hi/lo
    softmax_kernel<<<BATCH * SEQ, 256>>>(s_ptr, mask, ph, pl);

    // 6) merged M[b] = P[b] @ (V^T[b])^T  (M=2048, N=768, K=2048, batched)
    {
        dim3 grid(DIM / BN, SEQ / BM, BATCH);
        gemm_mma<1><<<grid, 256, GEMM_SMEM>>>(ph, pl, vth, vtl, nullptr, nullptr, mh, ml,
                                              SEQ, DIM, SEQ,
                                              (long long)SEQ * SEQ, (long long)DIM * SEQ,
                                              (long long)SEQ * DIM);
    }

    // 7) out = M @ fc_w^T + fc_b
    {
        dim3 grid(DIM / BN, MTOT / BM, 1);
        gemm_mma<0><<<grid, 256, GEMM_SMEM>>>(mh, ml, wfh, wfl, fc_b, out, nullptr, nullptr,
                                              MTOT, DIM, DIM, 0, 0, 0);
    }
}

// round 5
// speedup vs baseline: 2.0614x; 1.0028x over previous
#include <cuda_runtime.h>
#include <cuda_bf16.h>
#include <math.h>
#include <stdint.h>

typedef __nv_bfloat16 bf16;

#define BATCH 8
#define SEQ   2048
#define DIM   768
#define MTOT  (BATCH * SEQ)     // 16384

// ---- GEMM tile config (mma.sync path, sm_103-safe) ----
#define BM 128
#define BN 128
#define BK 32
#define ROWB 80                       // K-major padded row bytes (64B data + 16B pad)
#define ROWB_T 272                    // trans-B padded row bytes (256B data + 16B pad)
#define MATA_BYTES (128 * ROWB)       // 10240 (A hi or lo)
#define MATB_BYTES (128 * ROWB)       // 10240 (B K-major hi or lo)
#define MATBT_BYTES (32 * ROWB_T)     // 8704  (B trans hi or lo)
#define NSTAGES 4

// ---------------- device scratch (allocation-free rule) ----------------
__device__ bf16 g_xh[MTOT * DIM], g_xl[MTOT * DIM];     // query split
__device__ bf16 g_yh[MTOT * DIM], g_yl[MTOT * DIM];     // value split
__device__ bf16 g_wqh[DIM * DIM], g_wql[DIM * DIM];
__device__ bf16 g_wkh[DIM * DIM], g_wkl[DIM * DIM];
__device__ bf16 g_wvh[DIM * DIM], g_wvl[DIM * DIM];
__device__ bf16 g_wfh[DIM * DIM], g_wfl[DIM * DIM];
__device__ bf16 g_qh[MTOT * DIM], g_ql[MTOT * DIM];     // Q proj split
__device__ bf16 g_kh[MTOT * DIM], g_kl[MTOT * DIM];     // K proj split
__device__ bf16 g_vh[MTOT * DIM], g_vl[MTOT * DIM];     // V proj split [SEQ,DIM]
__device__ float g_s[(size_t)BATCH * SEQ * SEQ];         // scores fp32 (134MB)
__device__ bf16 g_ph[(size_t)BATCH * SEQ * SEQ];         // probs split
__device__ bf16 g_pl[(size_t)BATCH * SEQ * SEQ];
__device__ bf16 g_mh[MTOT * DIM], g_ml[MTOT * DIM];     // merged split

// ---------------- PTX helpers (all plain-sm_103 legal) ----------------
__device__ __forceinline__ uint32_t smem_u32(const void* p) {
    uint32_t a;
    asm("{ .reg .u64 t; cvta.to.shared.u64 t, %1; cvt.u32.u64 %0, t; }" : "=r"(a) : "l"(p));
    return a;
}
__device__ __forceinline__ void cp16(uint32_t s, const void* g) {
    asm volatile("cp.async.cg.shared.global [%0], [%1], 16;" :: "r"(s), "l"(g));
}
__device__ __forceinline__ void cp_commit() { asm volatile("cp.async.commit_group;" ::: "memory"); }
template <int N> __device__ __forceinline__ void cp_wait() {
    asm volatile("cp.async.wait_group %0;" :: "n"(N) : "memory");
}
__device__ __forceinline__ void ldmat_x4(uint32_t* r, uint32_t addr) {
    asm volatile("ldmatrix.sync.aligned.m8n8.x4.shared.b16 {%0,%1,%2,%3}, [%4];"
                 : "=r"(r[0]), "=r"(r[1]), "=r"(r[2]), "=r"(r[3]) : "r"(addr));
}
__device__ __forceinline__ void ldmat_x4_t(uint32_t* r, uint32_t addr) {
    asm volatile("ldmatrix.sync.aligned.m8n8.x4.trans.shared.b16 {%0,%1,%2,%3}, [%4];"
                 : "=r"(r[0]), "=r"(r[1]), "=r"(r[2]), "=r"(r[3]) : "r"(addr));
}
__device__ __forceinline__ void mma_bf16(float* c, const uint32_t* a, uint32_t b0, uint32_t b1) {
    asm volatile(
        "mma.sync.aligned.m16n8k16.row.col.f32.bf16.bf16.f32 "
        "{%0,%1,%2,%3}, {%4,%5,%6,%7}, {%8,%9}, {%0,%1,%2,%3};"
        : "+f"(c[0]), "+f"(c[1]), "+f"(c[2]), "+f"(c[3])
        : "r"(a[0]), "r"(a[1]), "r"(a[2]), "r"(a[3]), "r"(b0), "r"(b1));
}

// ---------------------------------------------------------------------------
// mma.sync GEMM, 3-term bf16 split: C = A*op(B) (+bias).
//   BTRANS=0: B is [N,K] row-major (K contiguous)  -> C = A @ B^T
//   BTRANS=1: B is [K,N] row-major (N contiguous)  -> C = A @ B
// EPI=0: fp32 C. EPI=1: bf16 hi/lo split C.
// grid: (N/BN, M/BM, batch); block: 256 threads (8 warps of 64x32).
// ---------------------------------------------------------------------------
template <int EPI, int BTRANS>
__global__ __launch_bounds__(256, 1) void gemm_mma(
    const bf16* __restrict__ Agh, const bf16* __restrict__ Agl,
    const bf16* __restrict__ Bgh, const bf16* __restrict__ Bgl,
    const float* __restrict__ bias,
    float* __restrict__ C, bf16* __restrict__ Ch, bf16* __restrict__ Cl,
    int M, int N, int K,
    long long sA, long long sB, long long sC)
{
    constexpr uint32_t BPART = BTRANS ? MATBT_BYTES : MATB_BYTES;
    constexpr uint32_t STAGE = 2 * MATA_BYTES + 2 * BPART;

    extern __shared__ char smem[];
    const int tid = threadIdx.x;
    const int wid = tid >> 5;
    const int lane = tid & 31;
    const int bz = blockIdx.z;
    Agh += bz * sA; Agl += bz * sA;
    Bgh += bz * sB; Bgl += bz * sB;
    const long long coff = bz * sC;

    const int row0 = blockIdx.y * BM;
    const int col0 = blockIdx.x * BN;
    const uint32_t smem_base = smem_u32(smem);

    const int wm = (wid >> 2) * 64;   // warp m offset in tile
    const int wn = (wid & 3) * 32;    // warp n offset in tile

    float acc[4][4][4];
#pragma unroll
    for (int i = 0; i < 4; i++)
#pragma unroll
        for (int j = 0; j < 4; j++)
#pragma unroll
            for (int t = 0; t < 4; t++) acc[i][j][t] = 0.f;

    const int NS = K / BK;

    auto load_stage = [&](int st, int k0) {
        const uint32_t base = smem_base + (uint32_t)st * STAGE;
#pragma unroll
        for (int i = 0; i < 2; i++) {              // A: 128 rows x 4 chunks
            int idx = tid + i * 256;
            int r = idx >> 2, c = idx & 3;
            uint32_t s = base + r * ROWB + c * 16;
            size_t g = (size_t)(row0 + r) * K + k0 + c * 8;
            cp16(s, Agh + g);
            cp16(s + MATA_BYTES, Agl + g);
        }
        const uint32_t bb = base + 2 * MATA_BYTES;
        if (BTRANS) {
#pragma unroll
            for (int i = 0; i < 2; i++) {          // B: 32 k-rows x 16 chunks
                int idx = tid + i * 256;
                int r = idx >> 4, c = idx & 15;
                uint32_t s = bb + r * ROWB_T + c * 16;
                size_t g = (size_t)(k0 + r) * N + col0 + c * 8;
                cp16(s, Bgh + g);
                cp16(s + MATBT_BYTES, Bgl + g);
            }
        } else {
#pragma unroll
            for (int i = 0; i < 2; i++) {          // B: 128 n-rows x 4 chunks
                int idx = tid + i * 256;
                int r = idx >> 2, c = idx & 3;
                uint32_t s = bb + r * ROWB + c * 16;
                size_t g = (size_t)(col0 + r) * K + k0 + c * 8;
                cp16(s, Bgh + g);
                cp16(s + MATB_BYTES, Bgl + g);
            }
        }
        cp_commit();
    };

    // ldmatrix lane address components
    const int lrow = lane & 15;                         // A: row within m16
    const int lkh  = lane >> 4;                         // A: k half (0/1)
    const int brow = (lane & 7) + ((lane >> 4) << 3);   // B !trans: n row within n16
    const int bkh  = (lane >> 3) & 1;                   // B !trans: k half
    const int tkrow = lane & 15;                        // B trans: k row within k16
    const int tnoff = (lane >> 4) << 3;                 // B trans: n offset (0/8)

    load_stage(0, 0);
    load_stage(1, BK);
    load_stage(2, 2 * BK);

    for (int s = 0; s < NS; s++) {
        if (s < NS - 2)      cp_wait<2>();   // stage s complete
        else if (s == NS - 2) cp_wait<1>();
        else                  cp_wait<0>();
        __syncthreads();
        if (s + 3 < NS) load_stage((s + 3) & 3, (s + 3) * BK);

        const uint32_t base = smem_base + (uint32_t)(s & 3) * STAGE;
        const uint32_t aB = base;
        const uint32_t bB = base + 2 * MATA_BYTES;

#pragma unroll
        for (int ks = 0; ks < 2; ks++) {
            uint32_t afh[4][4], afl[4][4];
#pragma unroll
            for (int im = 0; im < 4; im++) {
                uint32_t ad = aB + (uint32_t)((wm + im * 16 + lrow) * ROWB + ks * 32 + lkh * 16);
                ldmat_x4(afh[im], ad);
                ldmat_x4(afl[im], ad + MATA_BYTES);
            }
            uint32_t bfh[2][4], bfl[2][4];
#pragma unroll
            for (int ib = 0; ib < 2; ib++) {
                if (BTRANS) {
                    uint32_t bd = bB + (uint32_t)((ks * 16 + tkrow) * ROWB_T
                                                  + ((wn + ib * 16 + tnoff) << 1));
                    ldmat_x4_t(bfh[ib], bd);
                    ldmat_x4_t(bfl[ib], bd + MATBT_BYTES);
                } else {
                    uint32_t bd = bB + (uint32_t)((wn + ib * 16 + brow) * ROWB + ks * 32 + bkh * 16);
                    ldmat_x4(bfh[ib], bd);
                    ldmat_x4(bfl[ib], bd + MATB_BYTES);
                }
            }
#pragma unroll
            for (int im = 0; im < 4; im++) {
#pragma unroll
                for (int in4 = 0; in4 < 4; in4++) {
                    const int ib = in4 >> 1, hf = (in4 & 1) * 2;
                    mma_bf16(acc[im][in4], afh[im], bfh[ib][hf], bfh[ib][hf + 1]);
                    mma_bf16(acc[im][in4], afh[im], bfl[ib][hf], bfl[ib][hf + 1]);
                    mma_bf16(acc[im][in4], afl[im], bfh[ib][hf], bfh[ib][hf + 1]);
                }
            }
        }
        __syncthreads();
    }

    // ---- epilogue ----
    const int lane4 = lane >> 2;
    const int lanec = (lane & 3) * 2;
#pragma unroll
    for (int im = 0; im < 4; im++) {
#pragma unroll
        for (int in4 = 0; in4 < 4; in4++) {
            const int m0 = row0 + wm + im * 16 + lane4;
            const int nc = col0 + wn + in4 * 8 + lanec;
            float b0 = bias ? bias[nc] : 0.f;
            float b1 = bias ? bias[nc + 1] : 0.f;
            float v00 = acc[im][in4][0] + b0, v01 = acc[im][in4][1] + b1;
            float v10 = acc[im][in4][2] + b0, v11 = acc[im][in4][3] + b1;
            if (EPI == 0) {
                *(float2*)&C[coff + (long long)m0 * N + nc]       = make_float2(v00, v01);
                *(float2*)&C[coff + (long long)(m0 + 8) * N + nc] = make_float2(v10, v11);
            } else {
                bf16 h[2], l[2];
                h[0] = __float2bfloat16_rn(v00); l[0] = __float2bfloat16_rn(v00 - __bfloat162float(h[0]));
                h[1] = __float2bfloat16_rn(v01); l[1] = __float2bfloat16_rn(v01 - __bfloat162float(h[1]));
                *(uint32_t*)&Ch[coff + (long long)m0 * N + nc] = *(uint32_t*)h;
                *(uint32_t*)&Cl[coff + (long long)m0 * N + nc] = *(uint32_t*)l;
                h[0] = __float2bfloat16_rn(v10); l[0] = __float2bfloat16_rn(v10 - __bfloat162float(h[0]));
                h[1] = __float2bfloat16_rn(v11); l[1] = __float2bfloat16_rn(v11 - __bfloat162float(h[1]));
                *(uint32_t*)&Ch[coff + (long long)(m0 + 8) * N + nc] = *(uint32_t*)h;
                *(uint32_t*)&Cl[coff + (long long)(m0 + 8) * N + nc] = *(uint32_t*)l;
            }
        }
    }
}

// ---------------------------------------------------------------------------
// fp32 -> bf16 hi/lo split (elementwise, float4 vectorized)
// ---------------------------------------------------------------------------
__global__ __launch_bounds__(256) void split_kernel(
    const float* __restrict__ x, bf16* __restrict__ h, bf16* __restrict__ l, int n4)
{
    int i = blockIdx.x * 256 + threadIdx.x;
    if (i >= n4) return;
    float4 v = *(const float4*)&x[i * 4];
    bf16 hb[4], lb[4];
    float f[4] = {v.x, v.y, v.z, v.w};
#pragma unroll
    for (int j = 0; j < 4; j++) {
        hb[j] = __float2bfloat16_rn(f[j]);
        lb[j] = __float2bfloat16_rn(f[j] - __bfloat162float(hb[j]));
    }
    *(uint2*)&h[i * 4] = *(uint2*)hb;
    *(uint2*)&l[i * 4] = *(uint2*)lb;
}

// ---------------------------------------------------------------------------
// Masked softmax: reads fp32 S, writes bf16 hi/lo P (query mask folded in)
// ---------------------------------------------------------------------------
__device__ __forceinline__ float warp_max(float v) {
#pragma unroll
    for (int o = 16; o > 0; o >>= 1) v = fmaxf(v, __shfl_xor_sync(0xffffffffu, v, o));
    return v;
}
__device__ __forceinline__ float warp_sum(float v) {
#pragma unroll
    for (int o = 16; o > 0; o >>= 1) v += __shfl_xor_sync(0xffffffffu, v, o);
    return v;
}

__global__ __launch_bounds__(256) void softmax_kernel(
    const float* __restrict__ S, const int* __restrict__ mask,
    bf16* __restrict__ Ph, bf16* __restrict__ Pl)
{
    const long long row = blockIdx.x;          // b*SEQ + q
    const int b = (int)(row / SEQ);
    const int q = (int)(row % SEQ);
    const float* __restrict__ Srow = S + row * (long long)SEQ;
    const int* __restrict__ mrow = mask + (long long)b * SEQ;
    const int qm = mrow[q];

    __shared__ float red_max[8];
    __shared__ float red_sum[8];
    const int tid = threadIdx.x;
    const int wid = tid >> 5, lid = tid & 31;

    float vals[8];
    float m = -INFINITY;
#pragma unroll
    for (int i = 0; i < 8; i++) {
        int j = tid + i * 256;
        float s = mrow[j] ? Srow[j] : -INFINITY;
        vals[i] = s;
        m = fmaxf(m, s);
    }
    m = warp_max(m);
    if (lid == 0) red_max[wid] = m;
    __syncthreads();
    { float t = (lid < 8) ? red_max[lid] : -INFINITY; m = warp_max(t); }

    float sum = 0.f;
#pragma unroll
    for (int i = 0; i < 8; i++) {
        float e = __expf(vals[i] - m);
        vals[i] = e;
        sum += e;
    }
    sum = warp_sum(sum);
    if (lid == 0) red_sum[wid] = sum;
    __syncthreads();
    { float t = (lid < 8) ? red_sum[lid] : 0.f; sum = warp_sum(t); }

    const float scale = qm ? (1.f / sum) : 0.f;
#pragma unroll
    for (int i = 0; i < 8; i++) {
        int j = tid + i * 256;
        float p = vals[i] * scale;
        bf16 h = __float2bfloat16_rn(p);
        bf16 l = __float2bfloat16_rn(p - __bfloat162float(h));
        Ph[row * (long long)SEQ + j] = h;
        Pl[row * (long long)SEQ + j] = l;
    }
}

// ---------------------------------------------------------------------------
extern "C" void kernel_launch(void* const* d_in, const int* in_sizes, int n_in,
                              void* d_out, int out_size)
{
    const float* query = (const float*)d_in[0];
    const float* value = (const float*)d_in[1];
    const int*   mask  = (const int*)  d_in[2];
    const float* q_w   = (const float*)d_in[3];
    const float* q_b   = (const float*)d_in[4];
    const float* k_w   = (const float*)d_in[5];
    const float* k_b   = (const float*)d_in[6];
    const float* v_w   = (const float*)d_in[7];
    const float* v_b   = (const float*)d_in[8];
    const float* fc_w  = (const float*)d_in[9];
    const float* fc_b  = (const float*)d_in[10];
    float* out = (float*)d_out;

    const int SMEM_KM = NSTAGES * (2 * MATA_BYTES + 2 * MATB_BYTES);   // 163840
    const int SMEM_TR = NSTAGES * (2 * MATA_BYTES + 2 * MATBT_BYTES);  // 151552
    cudaFuncSetAttribute(gemm_mma<0,0>, cudaFuncAttributeMaxDynamicSharedMemorySize, SMEM_KM);
    cudaFuncSetAttribute(gemm_mma<1,0>, cudaFuncAttributeMaxDynamicSharedMemorySize, SMEM_KM);
    cudaFuncSetAttribute(gemm_mma<1,1>, cudaFuncAttributeMaxDynamicSharedMemorySize, SMEM_TR);

    bf16 *xh, *xl, *yh, *yl, *wqh, *wql, *wkh, *wkl, *wvh, *wvl, *wfh, *wfl;
    bf16 *qh, *ql, *kh, *kl, *vh, *vl, *ph, *pl, *mh, *ml;
    float *s_ptr;
    cudaGetSymbolAddress((void**)&xh, g_xh);   cudaGetSymbolAddress((void**)&xl, g_xl);
    cudaGetSymbolAddress((void**)&yh, g_yh);   cudaGetSymbolAddress((void**)&yl, g_yl);
    cudaGetSymbolAddress((void**)&wqh, g_wqh); cudaGetSymbolAddress((void**)&wql, g_wql);
    cudaGetSymbolAddress((void**)&wkh, g_wkh); cudaGetSymbolAddress((void**)&wkl, g_wkl);
    cudaGetSymbolAddress((void**)&wvh, g_wvh); cudaGetSymbolAddress((void**)&wvl, g_wvl);
    cudaGetSymbolAddress((void**)&wfh, g_wfh); cudaGetSymbolAddress((void**)&wfl, g_wfl);
    cudaGetSymbolAddress((void**)&qh, g_qh);   cudaGetSymbolAddress((void**)&ql, g_ql);
    cudaGetSymbolAddress((void**)&kh, g_kh);   cudaGetSymbolAddress((void**)&kl, g_kl);
    cudaGetSymbolAddress((void**)&vh, g_vh);   cudaGetSymbolAddress((void**)&vl, g_vl);
    cudaGetSymbolAddress((void**)&s_ptr, g_s);
    cudaGetSymbolAddress((void**)&ph, g_ph);   cudaGetSymbolAddress((void**)&pl, g_pl);
    cudaGetSymbolAddress((void**)&mh, g_mh);   cudaGetSymbolAddress((void**)&ml, g_ml);

    // 1) split inputs + weights to bf16 hi/lo
    {
        int n4 = MTOT * DIM / 4;
        split_kernel<<<(n4 + 255) / 256, 256>>>(query, xh, xl, n4);
        split_kernel<<<(n4 + 255) / 256, 256>>>(value, yh, yl, n4);
        int w4 = DIM * DIM / 4;
        split_kernel<<<(w4 + 255) / 256, 256>>>(q_w,  wqh, wql, w4);
        split_kernel<<<(w4 + 255) / 256, 256>>>(k_w,  wkh, wkl, w4);
        split_kernel<<<(w4 + 255) / 256, 256>>>(v_w,  wvh, wvl, w4);
        split_kernel<<<(w4 + 255) / 256, 256>>>(fc_w, wfh, wfl, w4);
    }

    // 2) projections (M=16384, N=768, K=768) — all emit bf16 hi/lo
    {
        dim3 grid(DIM / BN, MTOT / BM, 1);
        gemm_mma<1,0><<<grid, 256, SMEM_KM>>>(xh, xl, wqh, wql, q_b, nullptr, qh, ql,
                                              MTOT, DIM, DIM, 0, 0, 0);
        gemm_mma<1,0><<<grid, 256, SMEM_KM>>>(yh, yl, wkh, wkl, k_b, nullptr, kh, kl,
                                              MTOT, DIM, DIM, 0, 0, 0);
        gemm_mma<1,0><<<grid, 256, SMEM_KM>>>(yh, yl, wvh, wvl, v_b, nullptr, vh, vl,
                                              MTOT, DIM, DIM, 0, 0, 0);
    }

    // 3) scores S[b] = Q[b] @ K[b]^T  (M=N=2048, K=768, batched)
    {
        dim3 grid(SEQ / BN, SEQ / BM, BATCH);
        gemm_mma<0,0><<<grid, 256, SMEM_KM>>>(qh, ql, kh, kl, nullptr, s_ptr, nullptr, nullptr,
                                              SEQ, SEQ, DIM,
                                              (long long)SEQ * DIM, (long long)SEQ * DIM,
                                              (long long)SEQ * SEQ);
    }

    // 4) masked softmax -> P hi/lo
    softmax_kernel<<<BATCH * SEQ, 256>>>(s_ptr, mask, ph, pl);

    // 5) merged M[b] = P[b] @ V[b]  (M=2048, N=768, K=2048; B row-major [K,N] via trans)
    {
        dim3 grid(DIM / BN, SEQ / BM, BATCH);
        gemm_mma<1,1><<<grid, 256, SMEM_TR>>>(ph, pl, vh, vl, nullptr, nullptr, mh, ml,
                                              SEQ, DIM, SEQ,
                                              (long long)SEQ * SEQ, (long long)SEQ * DIM,
                                              (long long)SEQ * DIM);
    }

    // 6) out = M @ fc_w^T + fc_b
    {
        dim3 grid(DIM / BN, MTOT / BM, 1);
        gemm_mma<0,0><<<grid, 256, SMEM_KM>>>(mh, ml, wfh, wfl, fc_b, out, nullptr, nullptr,
                                              MTOT, DIM, DIM, 0, 0, 0);
    }
}

// round 6
// speedup vs baseline: 5.0945x; 2.4714x over previous
#include <cuda_runtime.h>
#include <cuda_bf16.h>
#include <math.h>
#include <stdint.h>

typedef __nv_bfloat16 bf16;

#define BATCH 8
#define SEQ   2048
#define DIM   768
#define MTOT  (BATCH * SEQ)     // 16384

// ---- GEMM tile config (mma.sync path, sm_103-safe) ----
#define BM 128
#define BN 128
#define BK 32
#define ROWB 80                       // K-major padded row bytes (64B data + 16B pad)
#define ROWB_T 272                    // trans-B padded row bytes (256B data + 16B pad)
#define MATA_BYTES (128 * ROWB)       // 10240 (A hi or lo)
#define MATB_BYTES (128 * ROWB)       // 10240 (B K-major hi or lo)
#define MATBT_BYTES (32 * ROWB_T)     // 8704  (B trans hi or lo)
#define NSTAGES 4

// ---------------- device scratch (allocation-free rule) ----------------
__device__ int  g_idx[BATCH * SEQ];                      // compact -> orig position
__device__ int  g_cnt[BATCH];                            // exact unmasked count
__device__ int  g_cntpad[BATCH];                         // padded to 128
__device__ bf16 g_xh[MTOT * DIM], g_xl[MTOT * DIM];     // query compact split
__device__ bf16 g_yh[MTOT * DIM], g_yl[MTOT * DIM];     // value compact split
__device__ bf16 g_wqh[DIM * DIM], g_wql[DIM * DIM];
__device__ bf16 g_wkh[DIM * DIM], g_wkl[DIM * DIM];
__device__ bf16 g_wvh[DIM * DIM], g_wvl[DIM * DIM];
__device__ bf16 g_wfh[DIM * DIM], g_wfl[DIM * DIM];
__device__ bf16 g_qh[MTOT * DIM], g_ql[MTOT * DIM];     // Q proj compact split
__device__ bf16 g_kh[MTOT * DIM], g_kl[MTOT * DIM];     // K proj compact split
__device__ bf16 g_vh[MTOT * DIM], g_vl[MTOT * DIM];     // V proj compact split
__device__ float g_s[(size_t)BATCH * SEQ * SEQ];         // scores fp32 (compact region)
__device__ bf16 g_ph[(size_t)BATCH * SEQ * SEQ];         // probs split
__device__ bf16 g_pl[(size_t)BATCH * SEQ * SEQ];
__device__ bf16 g_mh[MTOT * DIM], g_ml[MTOT * DIM];     // merged compact split

// ---------------- PTX helpers (all plain-sm_103 legal) ----------------
__device__ __forceinline__ uint32_t smem_u32(const void* p) {
    uint32_t a;
    asm("{ .reg .u64 t; cvta.to.shared.u64 t, %1; cvt.u32.u64 %0, t; }" : "=r"(a) : "l"(p));
    return a;
}
__device__ __forceinline__ void cp16(uint32_t s, const void* g) {
    asm volatile("cp.async.cg.shared.global [%0], [%1], 16;" :: "r"(s), "l"(g));
}
__device__ __forceinline__ void cp_commit() { asm volatile("cp.async.commit_group;" ::: "memory"); }
template <int N> __device__ __forceinline__ void cp_wait() {
    asm volatile("cp.async.wait_group %0;" :: "n"(N) : "memory");
}
__device__ __forceinline__ void ldmat_x4(uint32_t* r, uint32_t addr) {
    asm volatile("ldmatrix.sync.aligned.m8n8.x4.shared.b16 {%0,%1,%2,%3}, [%4];"
                 : "=r"(r[0]), "=r"(r[1]), "=r"(r[2]), "=r"(r[3]) : "r"(addr));
}
__device__ __forceinline__ void ldmat_x4_t(uint32_t* r, uint32_t addr) {
    asm volatile("ldmatrix.sync.aligned.m8n8.x4.trans.shared.b16 {%0,%1,%2,%3}, [%4];"
                 : "=r"(r[0]), "=r"(r[1]), "=r"(r[2]), "=r"(r[3]) : "r"(addr));
}
__device__ __forceinline__ void mma_bf16(float* c, const uint32_t* a, uint32_t b0, uint32_t b1) {
    asm volatile(
        "mma.sync.aligned.m16n8k16.row.col.f32.bf16.bf16.f32 "
        "{%0,%1,%2,%3}, {%4,%5,%6,%7}, {%8,%9}, {%0,%1,%2,%3};"
        : "+f"(c[0]), "+f"(c[1]), "+f"(c[2]), "+f"(c[3])
        : "r"(a[0]), "r"(a[1]), "r"(a[2]), "r"(a[3]), "r"(b0), "r"(b1));
}

// ---------------------------------------------------------------------------
// mma.sync GEMM, 3-term bf16 split, with optional per-batch device bounds:
//   mb[bz]: M tile bound (row0 >= mb -> exit); nb: N bound; kb: K bound (NS).
//   scat/scnt: fp32 epilogue row scatter (compact -> orig) with exact count guard.
// ---------------------------------------------------------------------------
template <int EPI, int BTRANS>
__global__ __launch_bounds__(256, 1) void gemm_mma(
    const bf16* __restrict__ Agh, const bf16* __restrict__ Agl,
    const bf16* __restrict__ Bgh, const bf16* __restrict__ Bgl,
    const float* __restrict__ bias,
    float* __restrict__ C, bf16* __restrict__ Ch, bf16* __restrict__ Cl,
    int M, int N, int K,
    long long sA, long long sB, long long sC,
    const int* __restrict__ mb, const int* __restrict__ nb, const int* __restrict__ kb,
    const int* __restrict__ scat, const int* __restrict__ scnt)
{
    constexpr uint32_t BPART = BTRANS ? MATBT_BYTES : MATB_BYTES;
    constexpr uint32_t STAGE = 2 * MATA_BYTES + 2 * BPART;

    extern __shared__ char smem[];
    const int tid = threadIdx.x;
    const int wid = tid >> 5;
    const int lane = tid & 31;
    const int bz = blockIdx.z;

    const int row0 = blockIdx.y * BM;
    const int col0 = blockIdx.x * BN;
    if (mb && row0 >= mb[bz]) return;
    if (nb && col0 >= nb[bz]) return;
    const int NS = (kb ? kb[bz] : K) / BK;

    Agh += bz * sA; Agl += bz * sA;
    Bgh += bz * sB; Bgl += bz * sB;
    const long long coff = bz * sC;
    const uint32_t smem_base = smem_u32(smem);

    const int wm = (wid >> 2) * 64;   // warp m offset in tile
    const int wn = (wid & 3) * 32;    // warp n offset in tile

    float acc[4][4][4];
#pragma unroll
    for (int i = 0; i < 4; i++)
#pragma unroll
        for (int j = 0; j < 4; j++)
#pragma unroll
            for (int t = 0; t < 4; t++) acc[i][j][t] = 0.f;

    auto load_stage = [&](int st, int k0) {
        const uint32_t base = smem_base + (uint32_t)st * STAGE;
#pragma unroll
        for (int i = 0; i < 2; i++) {              // A: 128 rows x 4 chunks
            int idx = tid + i * 256;
            int r = idx >> 2, c = idx & 3;
            uint32_t s = base + r * ROWB + c * 16;
            size_t g = (size_t)(row0 + r) * K + k0 + c * 8;
            cp16(s, Agh + g);
            cp16(s + MATA_BYTES, Agl + g);
        }
        const uint32_t bb = base + 2 * MATA_BYTES;
        if (BTRANS) {
#pragma unroll
            for (int i = 0; i < 2; i++) {          // B: 32 k-rows x 16 chunks
                int idx = tid + i * 256;
                int r = idx >> 4, c = idx & 15;
                uint32_t s = bb + r * ROWB_T + c * 16;
                size_t g = (size_t)(k0 + r) * N + col0 + c * 8;
                cp16(s, Bgh + g);
                cp16(s + MATBT_BYTES, Bgl + g);
            }
        } else {
#pragma unroll
            for (int i = 0; i < 2; i++) {          // B: 128 n-rows x 4 chunks
                int idx = tid + i * 256;
                int r = idx >> 2, c = idx & 3;
                uint32_t s = bb + r * ROWB + c * 16;
                size_t g = (size_t)(col0 + r) * K + k0 + c * 8;
                cp16(s, Bgh + g);
                cp16(s + MATB_BYTES, Bgl + g);
            }
        }
        cp_commit();
    };

    const int lrow = lane & 15;
    const int lkh  = lane >> 4;
    const int brow = (lane & 7) + ((lane >> 4) << 3);
    const int bkh  = (lane >> 3) & 1;
    const int tkrow = lane & 15;
    const int tnoff = (lane >> 4) << 3;

    load_stage(0, 0);          // NS >= 4 in all uses (cntpad >= 128)
    load_stage(1, BK);
    load_stage(2, 2 * BK);

    for (int s = 0; s < NS; s++) {
        if (s < NS - 2)       cp_wait<2>();
        else if (s == NS - 2) cp_wait<1>();
        else                  cp_wait<0>();
        __syncthreads();
        if (s + 3 < NS) load_stage((s + 3) & 3, (s + 3) * BK);

        const uint32_t base = smem_base + (uint32_t)(s & 3) * STAGE;
        const uint32_t aB = base;
        const uint32_t bB = base + 2 * MATA_BYTES;

#pragma unroll
        for (int ks = 0; ks < 2; ks++) {
            uint32_t afh[4][4], afl[4][4];
#pragma unroll
            for (int im = 0; im < 4; im++) {
                uint32_t ad = aB + (uint32_t)((wm + im * 16 + lrow) * ROWB + ks * 32 + lkh * 16);
                ldmat_x4(afh[im], ad);
                ldmat_x4(afl[im], ad + MATA_BYTES);
            }
            uint32_t bfh[2][4], bfl[2][4];
#pragma unroll
            for (int ib = 0; ib < 2; ib++) {
                if (BTRANS) {
                    uint32_t bd = bB + (uint32_t)((ks * 16 + tkrow) * ROWB_T
                                                  + ((wn + ib * 16 + tnoff) << 1));
                    ldmat_x4_t(bfh[ib], bd);
                    ldmat_x4_t(bfl[ib], bd + MATBT_BYTES);
                } else {
                    uint32_t bd = bB + (uint32_t)((wn + ib * 16 + brow) * ROWB + ks * 32 + bkh * 16);
                    ldmat_x4(bfh[ib], bd);
                    ldmat_x4(bfl[ib], bd + MATB_BYTES);
                }
            }
#pragma unroll
            for (int im = 0; im < 4; im++) {
#pragma unroll
                for (int in4 = 0; in4 < 4; in4++) {
                    const int ib = in4 >> 1, hf = (in4 & 1) * 2;
                    mma_bf16(acc[im][in4], afh[im], bfh[ib][hf], bfh[ib][hf + 1]);
                    mma_bf16(acc[im][in4], afh[im], bfl[ib][hf], bfl[ib][hf + 1]);
                    mma_bf16(acc[im][in4], afl[im], bfh[ib][hf], bfh[ib][hf + 1]);
                }
            }
        }
        __syncthreads();
    }

    // ---- epilogue ----
    const int lane4 = lane >> 2;
    const int lanec = (lane & 3) * 2;
#pragma unroll
    for (int im = 0; im < 4; im++) {
#pragma unroll
        for (int in4 = 0; in4 < 4; in4++) {
            const int mc = row0 + wm + im * 16 + lane4;     // compact row
            const int nc = col0 + wn + in4 * 8 + lanec;
            float b0 = bias ? bias[nc] : 0.f;
            float b1 = bias ? bias[nc + 1] : 0.f;
            float v00 = acc[im][in4][0] + b0, v01 = acc[im][in4][1] + b1;
            float v10 = acc[im][in4][2] + b0, v11 = acc[im][in4][3] + b1;
            if (EPI == 0) {
                if (scat) {
                    const int c0 = scnt[bz];
                    if (mc < c0) {
                        int o = scat[bz * SEQ + mc];
                        *(float2*)&C[coff + (long long)o * N + nc] = make_float2(v00, v01);
                    }
                    if (mc + 8 < c0) {
                        int o = scat[bz * SEQ + mc + 8];
                        *(float2*)&C[coff + (long long)o * N + nc] = make_float2(v10, v11);
                    }
                } else {
                    *(float2*)&C[coff + (long long)mc * N + nc]       = make_float2(v00, v01);
                    *(float2*)&C[coff + (long long)(mc + 8) * N + nc] = make_float2(v10, v11);
                }
            } else {
                bf16 h[2], l[2];
                h[0] = __float2bfloat16_rn(v00); l[0] = __float2bfloat16_rn(v00 - __bfloat162float(h[0]));
                h[1] = __float2bfloat16_rn(v01); l[1] = __float2bfloat16_rn(v01 - __bfloat162float(h[1]));
                *(uint32_t*)&Ch[coff + (long long)mc * N + nc] = *(uint32_t*)h;
                *(uint32_t*)&Cl[coff + (long long)mc * N + nc] = *(uint32_t*)l;
                h[0] = __float2bfloat16_rn(v10); l[0] = __float2bfloat16_rn(v10 - __bfloat162float(h[0]));
                h[1] = __float2bfloat16_rn(v11); l[1] = __float2bfloat16_rn(v11 - __bfloat162float(h[1]));
                *(uint32_t*)&Ch[coff + (long long)(mc + 8) * N + nc] = *(uint32_t*)h;
                *(uint32_t*)&Cl[coff + (long long)(mc + 8) * N + nc] = *(uint32_t*)l;
            }
        }
    }
}

// ---------------------------------------------------------------------------
// Per-batch mask compaction: deterministic inclusive scan (Hillis-Steele).
// ---------------------------------------------------------------------------
__global__ __launch_bounds__(1024) void mask_scan_kernel(
    const int* __restrict__ mask, int* __restrict__ idx,
    int* __restrict__ cnt, int* __restrict__ cntpad)
{
    __shared__ int sa[2048], sb[2048];
    const int b = blockIdx.x;
    const int t = threadIdx.x;
    const int* m = mask + b * SEQ;
    sa[t] = (m[t] != 0);
    sa[t + 1024] = (m[t + 1024] != 0);
    __syncthreads();
    int* src = sa; int* dst = sb;
    for (int off = 1; off < 2048; off <<= 1) {
#pragma unroll
        for (int k = 0; k < 2; k++) {
            int i = t + k * 1024;
            dst[i] = src[i] + (i >= off ? src[i - off] : 0);
        }
        __syncthreads();
        int* tmp = src; src = dst; dst = tmp;
    }
#pragma unroll
    for (int k = 0; k < 2; k++) {
        int i = t + k * 1024;
        if (m[i] != 0) idx[b * SEQ + src[i] - 1] = i;
    }
    if (t == 0) {
        int c = src[2047];
        cnt[b] = c;
        cntpad[b] = (c + 127) & ~127;
    }
}

// ---------------------------------------------------------------------------
// Gather unmasked rows of fp32 input -> compact bf16 hi/lo (zero padding rows)
// grid (SEQ, BATCH) x 192 threads
// ---------------------------------------------------------------------------
__global__ __launch_bounds__(192) void gather_split_kernel(
    const float* __restrict__ in, const int* __restrict__ idx,
    const int* __restrict__ cnt, const int* __restrict__ cntpad,
    bf16* __restrict__ h, bf16* __restrict__ l)
{
    const int b = blockIdx.y, j = blockIdx.x;
    if (j >= cntpad[b]) return;
    const int c = threadIdx.x * 4;
    const size_t dsti = ((size_t)b * SEQ + j) * DIM + c;
    bf16 hb[4], lb[4];
    if (j < cnt[b]) {
        int s = idx[b * SEQ + j];
        float4 v = *(const float4*)&in[((size_t)b * SEQ + s) * DIM + c];
        float f[4] = {v.x, v.y, v.z, v.w};
#pragma unroll
        for (int k = 0; k < 4; k++) {
            hb[k] = __float2bfloat16_rn(f[k]);
            lb[k] = __float2bfloat16_rn(f[k] - __bfloat162float(hb[k]));
        }
    } else {
#pragma unroll
        for (int k = 0; k < 4; k++) { hb[k] = __float2bfloat16_rn(0.f); lb[k] = hb[k]; }
    }
    *(uint2*)&h[dsti] = *(uint2*)hb;
    *(uint2*)&l[dsti] = *(uint2*)lb;
}

// ---------------------------------------------------------------------------
// Split 4 weight matrices in one launch (blockIdx.y selects matrix)
// ---------------------------------------------------------------------------
__global__ __launch_bounds__(256) void weight_split4_kernel(
    const float* __restrict__ w0, const float* __restrict__ w1,
    const float* __restrict__ w2, const float* __restrict__ w3,
    bf16* __restrict__ h0, bf16* __restrict__ l0, bf16* __restrict__ h1, bf16* __restrict__ l1,
    bf16* __restrict__ h2, bf16* __restrict__ l2, bf16* __restrict__ h3, bf16* __restrict__ l3)
{
    const int n4 = DIM * DIM / 4;
    int i = blockIdx.x * 256 + threadIdx.x;
    if (i >= n4) return;
    const float* w; bf16 *h, *l;
    switch (blockIdx.y) {
        case 0: w = w0; h = h0; l = l0; break;
        case 1: w = w1; h = h1; l = l1; break;
        case 2: w = w2; h = h2; l = l2; break;
        default: w = w3; h = h3; l = l3; break;
    }
    float4 v = *(const float4*)&w[i * 4];
    float f[4] = {v.x, v.y, v.z, v.w};
    bf16 hb[4], lb[4];
#pragma unroll
    for (int k = 0; k < 4; k++) {
        hb[k] = __float2bfloat16_rn(f[k]);
        lb[k] = __float2bfloat16_rn(f[k] - __bfloat162float(hb[k]));
    }
    *(uint2*)&h[i * 4] = *(uint2*)hb;
    *(uint2*)&l[i * 4] = *(uint2*)lb;
}

// ---------------------------------------------------------------------------
// Fill all output rows with fc bias (masked-query rows keep this value)
// ---------------------------------------------------------------------------
__global__ __launch_bounds__(256) void bias_fill_kernel(
    float* __restrict__ out, const float* __restrict__ bias)
{
    int i = blockIdx.x * 256 + threadIdx.x;    // float4 index
    int c = (i * 4) % DIM;
    float4 v = *(const float4*)&bias[c];
    *(float4*)&out[(size_t)i * 4] = v;
}

// ---------------------------------------------------------------------------
// Compact softmax: rows/cols are compacted (all real cols unmasked).
// Padding rows -> P=0; cols in [cnt, cntpad) -> P=0.
// ---------------------------------------------------------------------------
__device__ __forceinline__ float warp_max(float v) {
#pragma unroll
    for (int o = 16; o > 0; o >>= 1) v = fmaxf(v, __shfl_xor_sync(0xffffffffu, v, o));
    return v;
}
__device__ __forceinline__ float warp_sum(float v) {
#pragma unroll
    for (int o = 16; o > 0; o >>= 1) v += __shfl_xor_sync(0xffffffffu, v, o);
    return v;
}

__global__ __launch_bounds__(256) void softmax_kernel(
    const float* __restrict__ S, const int* __restrict__ cnt, const int* __restrict__ cntpad,
    bf16* __restrict__ Ph, bf16* __restrict__ Pl)
{
    const int b = blockIdx.x >> 11;
    const int j = blockIdx.x & (SEQ - 1);
    const int cp = cntpad[b];
    if (j >= cp) return;
    const int cn = cnt[b];
    const long long row = (long long)b * SEQ + j;
    const float* __restrict__ Srow = S + row * SEQ;

    __shared__ float red_max[8];
    __shared__ float red_sum[8];
    const int tid = threadIdx.x;
    const int wid = tid >> 5, lid = tid & 31;

    float vals[8];
    float m = -INFINITY;
#pragma unroll
    for (int i = 0; i < 8; i++) {
        int c = tid + i * 256;
        float s = (c < cn) ? Srow[c] : -INFINITY;
        vals[i] = s;
        m = fmaxf(m, s);
    }
    m = warp_max(m);
    if (lid == 0) red_max[wid] = m;
    __syncthreads();
    { float t = (lid < 8) ? red_max[lid] : -INFINITY; m = warp_max(t); }

    float sum = 0.f;
#pragma unroll
    for (int i = 0; i < 8; i++) {
        float e = __expf(vals[i] - m);
        vals[i] = e;
        sum += e;
    }
    sum = warp_sum(sum);
    if (lid == 0) red_sum[wid] = sum;
    __syncthreads();
    { float t = (lid < 8) ? red_sum[lid] : 0.f; sum = warp_sum(t); }

    const float scale = (j < cn) ? (1.f / sum) : 0.f;   // padded rows -> all-zero P
#pragma unroll
    for (int i = 0; i < 8; i++) {
        int c = tid + i * 256;
        if (c < cp) {
            float p = (c < cn) ? vals[i] * scale : 0.f;
            bf16 h = __float2bfloat16_rn(p);
            bf16 l = __float2bfloat16_rn(p - __bfloat162float(h));
            Ph[row * SEQ + c] = h;
            Pl[row * SEQ + c] = l;
        }
    }
}

// ---------------------------------------------------------------------------
extern "C" void kernel_launch(void* const* d_in, const int* in_sizes, int n_in,
                              void* d_out, int out_size)
{
    const float* query = (const float*)d_in[0];
    const float* value = (const float*)d_in[1];
    const int*   mask  = (const int*)  d_in[2];
    const float* q_w   = (const float*)d_in[3];
    const float* q_b   = (const float*)d_in[4];
    const float* k_w   = (const float*)d_in[5];
    const float* k_b   = (const float*)d_in[6];
    const float* v_w   = (const float*)d_in[7];
    const float* v_b   = (const float*)d_in[8];
    const float* fc_w  = (const float*)d_in[9];
    const float* fc_b  = (const float*)d_in[10];
    float* out = (float*)d_out;

    const int SMEM_KM = NSTAGES * (2 * MATA_BYTES + 2 * MATB_BYTES);   // 163840
    const int SMEM_TR = NSTAGES * (2 * MATA_BYTES + 2 * MATBT_BYTES);  // 151552
    cudaFuncSetAttribute(gemm_mma<0,0>, cudaFuncAttributeMaxDynamicSharedMemorySize, SMEM_KM);
    cudaFuncSetAttribute(gemm_mma<1,0>, cudaFuncAttributeMaxDynamicSharedMemorySize, SMEM_KM);
    cudaFuncSetAttribute(gemm_mma<1,1>, cudaFuncAttributeMaxDynamicSharedMemorySize, SMEM_TR);

    int *idxp, *cntp, *cpp;
    bf16 *xh, *xl, *yh, *yl, *wqh, *wql, *wkh, *wkl, *wvh, *wvl, *wfh, *wfl;
    bf16 *qh, *ql, *kh, *kl, *vh, *vl, *ph, *pl, *mh, *ml;
    float *s_ptr;
    cudaGetSymbolAddress((void**)&idxp, g_idx);
    cudaGetSymbolAddress((void**)&cntp, g_cnt);
    cudaGetSymbolAddress((void**)&cpp, g_cntpad);
    cudaGetSymbolAddress((void**)&xh, g_xh);   cudaGetSymbolAddress((void**)&xl, g_xl);
    cudaGetSymbolAddress((void**)&yh, g_yh);   cudaGetSymbolAddress((void**)&yl, g_yl);
    cudaGetSymbolAddress((void**)&wqh, g_wqh); cudaGetSymbolAddress((void**)&wql, g_wql);
    cudaGetSymbolAddress((void**)&wkh, g_wkh); cudaGetSymbolAddress((void**)&wkl, g_wkl);
    cudaGetSymbolAddress((void**)&wvh, g_wvh); cudaGetSymbolAddress((void**)&wvl, g_wvl);
    cudaGetSymbolAddress((void**)&wfh, g_wfh); cudaGetSymbolAddress((void**)&wfl, g_wfl);
    cudaGetSymbolAddress((void**)&qh, g_qh);   cudaGetSymbolAddress((void**)&ql, g_ql);
    cudaGetSymbolAddress((void**)&kh, g_kh);   cudaGetSymbolAddress((void**)&kl, g_kl);
    cudaGetSymbolAddress((void**)&vh, g_vh);   cudaGetSymbolAddress((void**)&vl, g_vl);
    cudaGetSymbolAddress((void**)&s_ptr, g_s);
    cudaGetSymbolAddress((void**)&ph, g_ph);   cudaGetSymbolAddress((void**)&pl, g_pl);
    cudaGetSymbolAddress((void**)&mh, g_mh);   cudaGetSymbolAddress((void**)&ml, g_ml);

    // 1) mask compaction
    mask_scan_kernel<<<BATCH, 1024>>>(mask, idxp, cntp, cpp);

    // 2) gather + split inputs (compact rows); split weights (1 launch)
    {
        dim3 gg(SEQ, BATCH);
        gather_split_kernel<<<gg, 192>>>(query, idxp, cntp, cpp, xh, xl);
        gather_split_kernel<<<gg, 192>>>(value, idxp, cntp, cpp, yh, yl);
        weight_split4_kernel<<<dim3(576, 4), 256>>>(q_w, k_w, v_w, fc_w,
                                                    wqh, wql, wkh, wkl, wvh, wvl, wfh, wfl);
    }

    // 3) pre-fill output with fc bias (covers masked-query rows)
    bias_fill_kernel<<<MTOT * DIM / 4 / 256, 256>>>(out, fc_b);

    // 4) projections on compact rows (per-batch M bound)
    {
        dim3 grid(DIM / BN, SEQ / BM, BATCH);
        const long long sa = (long long)SEQ * DIM;
        gemm_mma<1,0><<<grid, 256, SMEM_KM>>>(xh, xl, wqh, wql, q_b, nullptr, qh, ql,
                                              SEQ, DIM, DIM, sa, 0, sa,
                                              cpp, nullptr, nullptr, nullptr, nullptr);
        gemm_mma<1,0><<<grid, 256, SMEM_KM>>>(yh, yl, wkh, wkl, k_b, nullptr, kh, kl,
                                              SEQ, DIM, DIM, sa, 0, sa,
                                              cpp, nullptr, nullptr, nullptr, nullptr);
        gemm_mma<1,0><<<grid, 256, SMEM_KM>>>(yh, yl, wvh, wvl, v_b, nullptr, vh, vl,
                                              SEQ, DIM, DIM, sa, 0, sa,
                                              cpp, nullptr, nullptr, nullptr, nullptr);
    }

    // 5) scores (compact M and N)
    {
        dim3 grid(SEQ / BN, SEQ / BM, BATCH);
        gemm_mma<0,0><<<grid, 256, SMEM_KM>>>(qh, ql, kh, kl, nullptr, s_ptr, nullptr, nullptr,
                                              SEQ, SEQ, DIM,
                                              (long long)SEQ * DIM, (long long)SEQ * DIM,
                                              (long long)SEQ * SEQ,
                                              cpp, cpp, nullptr, nullptr, nullptr);
    }

    // 6) compact softmax -> P hi/lo
    softmax_kernel<<<BATCH * SEQ, 256>>>(s_ptr, cntp, cpp, ph, pl);

    // 7) merged = P @ V (compact M and K)
    {
        dim3 grid(DIM / BN, SEQ / BM, BATCH);
        gemm_mma<1,1><<<grid, 256, SMEM_TR>>>(ph, pl, vh, vl, nullptr, nullptr, mh, ml,
                                              SEQ, DIM, SEQ,
                                              (long long)SEQ * SEQ, (long long)SEQ * DIM,
                                              (long long)SEQ * DIM,
                                              cpp, nullptr, cpp, nullptr, nullptr);
    }

    // 8) out = scatter(fc(merged)) + fc_b (compact M, scatter rows)
    {
        dim3 grid(DIM / BN, SEQ / BM, BATCH);
        gemm_mma<0,0><<<grid, 256, SMEM_KM>>>(mh, ml, wfh, wfl, fc_b, out, nullptr, nullptr,
                                              SEQ, DIM, DIM,
                                              (long long)SEQ * DIM, 0, (long long)SEQ * DIM,
                                              cpp, nullptr, nullptr, idxp, cntp);
    }
}